// round 10
// baseline (speedup 1.0000x reference)
#include <cuda_runtime.h>
#include <math.h>

#define GRID  592            /* 148 SMs x 4 CTAs: one exact wave */
#define TPB   256
#define NB_N  472            /* NLL blocks  (~284 KB traffic each) */
#define NB_W1 60             /* W1 blocks   (~280 KB each); rest -> W2 */
#define DEPTH 3
#define NSTG  256            /* f4 per stream per NLL stage (4 KB)  */
#define WSTG  512            /* f4 per W stage (8 KB)               */

__device__ float g_part_nll[GRID];
__device__ float g_part_w1[GRID];
__device__ float g_part_w2[GRID];
__device__ unsigned int g_count = 0;   // atomicInc wraps to 0 each launch

static __device__ __forceinline__ unsigned smem_u32(const void* p) {
    unsigned a;
    asm("{ .reg .u64 t; cvta.to.shared.u64 t, %1; cvt.u32.u64 %0, t; }"
        : "=r"(a) : "l"(p));
    return a;
}
static __device__ __forceinline__ void mbar_init(unsigned mb, unsigned cnt) {
    asm volatile("mbarrier.init.shared::cta.b64 [%0], %1;" :: "r"(mb), "r"(cnt) : "memory");
}
static __device__ __forceinline__ void mbar_expect(unsigned mb, unsigned bytes) {
    asm volatile("mbarrier.arrive.expect_tx.shared::cta.b64 _, [%0], %1;"
                 :: "r"(mb), "r"(bytes) : "memory");
}
static __device__ __forceinline__ void bulk_g2s(unsigned dst, const void* src,
                                                unsigned bytes, unsigned mb) {
    asm volatile("cp.async.bulk.shared::cta.global.mbarrier::complete_tx::bytes "
                 "[%0], [%1], %2, [%3];"
                 :: "r"(dst), "l"(src), "r"(bytes), "r"(mb) : "memory");
}
static __device__ __forceinline__ void mbar_wait(unsigned mb, unsigned ph) {
    asm volatile(
        "{\n\t.reg .pred P;\n\t"
        "LAB%=:\n\t"
        "mbarrier.try_wait.parity.acquire.cta.shared::cta.b64 P, [%0], %1, 0x989680;\n\t"
        "@!P bra LAB%=;\n\t}"
        :: "r"(mb), "r"(ph) : "memory");
}

// log2(picked): picked = label ? p : 1-p, clamped at 1e-8.
static __device__ __forceinline__ float pick_lg2(float p, unsigned int l) {
    float g = __uint_as_float(l * 0x40800000u + 0xBF800000u);  // l? +0.0f : -1.0f
    float pick = fmaxf(fabsf(p + g), 1e-8f);
    return __log2f(pick);
}
static __device__ __forceinline__ float e4(float4 p, uint4 l) {
    return (pick_lg2(p.x, l.x) + pick_lg2(p.y, l.y))
         + (pick_lg2(p.z, l.z) + pick_lg2(p.w, l.w));
}
static __device__ __forceinline__ float sq4(float4 v, float a) {
    a = fmaf(v.x, v.x, a); a = fmaf(v.y, v.y, a);
    a = fmaf(v.z, v.z, a); a = fmaf(v.w, v.w, a);
    return a;
}
static __device__ __forceinline__ float warp_red(float v) {
    #pragma unroll
    for (int o = 16; o; o >>= 1) v += __shfl_down_sync(0xFFFFFFFFu, v, o);
    return v;
}
static __device__ __forceinline__ double warp_red_d(double v) {
    #pragma unroll
    for (int o = 16; o; o >>= 1) v += __shfl_down_sync(0xFFFFFFFFu, v, o);
    return v;
}

extern "C" __global__ void __launch_bounds__(TPB, 4)
fused_kernel(const float4* __restrict__ p4,
             const uint4*  __restrict__ l4,
             const float4* __restrict__ w1,
             const float4* __restrict__ w2,
             float* __restrict__ out,
             int nq, int nw1, int nw2,
             int chunk_n, int chunk_w1, int chunk_w2, double invN) {
    __shared__ __align__(128) unsigned char sbuf[DEPTH][8192];
    __shared__ __align__(8)   unsigned long long smbar[DEPTH];

    const int tid = threadIdx.x;
    const int bid = blockIdx.x;

    unsigned mb[DEPTH];
    #pragma unroll
    for (int s = 0; s < DEPTH; s++) mb[s] = smem_u32(&smbar[s]);
    if (tid == 0) {
        #pragma unroll
        for (int s = 0; s < DEPTH; s++) mbar_init(mb[s], 1);
        asm volatile("fence.proxy.async.shared::cta;" ::: "memory");
    }
    __syncthreads();

    float accL = 0.0f, a1 = 0.0f, a2 = 0.0f;

    if (bid < NB_N) {
        // ---- NLL stream: probs + labels, 3-deep bulk-async pipeline ----
        const int base  = bid * chunk_n;
        const int end   = min(nq, base + chunk_n);
        const int total = end - base;
        const int nst   = (total + NSTG - 1) / NSTG;

        // prologue: stages 0..DEPTH-1
        if (tid == 0) {
            #pragma unroll
            for (int k = 0; k < DEPTH; k++) {
                if (k < nst) {
                    int cnt = min(NSTG, total - k * NSTG);
                    mbar_expect(mb[k], (unsigned)(2 * cnt * 16));
                    bulk_g2s(smem_u32(&sbuf[k][0]),    p4 + base + k * NSTG, cnt * 16, mb[k]);
                    bulk_g2s(smem_u32(&sbuf[k][4096]), l4 + base + k * NSTG, cnt * 16, mb[k]);
                }
            }
        }
        for (int k = 0; k < nst; k++) {
            const int b  = k % DEPTH;
            const int ph = (k / DEPTH) & 1;
            mbar_wait(mb[b], (unsigned)ph);
            const int cnt = min(NSTG, total - k * NSTG);
            const float4* sp = (const float4*)&sbuf[b][0];
            const uint4*  sl = (const uint4*)&sbuf[b][4096];
            if (tid < cnt) accL += e4(sp[tid], sl[tid]);   // NSTG==TPB: one iter
            __syncthreads();
            const int kn = k + DEPTH;
            if (tid == 0 && kn < nst) {
                int cn = min(NSTG, total - kn * NSTG);
                mbar_expect(mb[b], (unsigned)(2 * cn * 16));
                bulk_g2s(smem_u32(&sbuf[b][0]),    p4 + base + kn * NSTG, cn * 16, mb[b]);
                bulk_g2s(smem_u32(&sbuf[b][4096]), l4 + base + kn * NSTG, cn * 16, mb[b]);
            }
        }
    } else {
        // ---- W sum-of-squares stream ----
        const bool isW1 = (bid < NB_N + NB_W1);
        const float4* w   = isW1 ? w1 : w2;
        const int     bb  = isW1 ? (bid - NB_N) : (bid - NB_N - NB_W1);
        const int     ch  = isW1 ? chunk_w1 : chunk_w2;
        const int     nw  = isW1 ? nw1 : nw2;
        const int base  = bb * ch;
        const int end   = min(nw, base + ch);
        const int total = end - base;
        const int nst   = (total + WSTG - 1) / WSTG;

        if (tid == 0) {
            #pragma unroll
            for (int k = 0; k < DEPTH; k++) {
                if (k < nst) {
                    int cnt = min(WSTG, total - k * WSTG);
                    mbar_expect(mb[k], (unsigned)(cnt * 16));
                    bulk_g2s(smem_u32(&sbuf[k][0]), w + base + k * WSTG, cnt * 16, mb[k]);
                }
            }
        }
        float s0 = 0.0f, s1 = 0.0f;
        for (int k = 0; k < nst; k++) {
            const int b  = k % DEPTH;
            const int ph = (k / DEPTH) & 1;
            mbar_wait(mb[b], (unsigned)ph);
            const int cnt = min(WSTG, total - k * WSTG);
            const float4* sw = (const float4*)&sbuf[b][0];
            if (tid < cnt)       s0 = sq4(sw[tid], s0);
            if (tid + TPB < cnt) s1 = sq4(sw[tid + TPB], s1);
            __syncthreads();
            const int kn = k + DEPTH;
            if (tid == 0 && kn < nst) {
                int cn = min(WSTG, total - kn * WSTG);
                mbar_expect(mb[b], (unsigned)(cn * 16));
                bulk_g2s(smem_u32(&sbuf[b][0]), w + base + kn * WSTG, cn * 16, mb[b]);
            }
        }
        float sw_acc = s0 + s1;
        if (isW1) a1 = sw_acc; else a2 = sw_acc;
    }

    // ---- Block reduction + last-block finish ----
    __shared__ float shL[8], sh1[8], sh2[8];
    __shared__ bool  is_last;
    const int lane = tid & 31;
    const int wrp  = tid >> 5;
    accL = warp_red(accL);
    a1   = warp_red(a1);
    a2   = warp_red(a2);
    if (lane == 0) { shL[wrp] = accL; sh1[wrp] = a1; sh2[wrp] = a2; }
    __syncthreads();
    if (tid == 0) {
        float vL = 0.0f, v1 = 0.0f, v2 = 0.0f;
        #pragma unroll
        for (int k = 0; k < 8; k++) { vL += shL[k]; v1 += sh1[k]; v2 += sh2[k]; }
        g_part_nll[bid] = vL;
        g_part_w1[bid]  = v1;
        g_part_w2[bid]  = v2;
        __threadfence();
        unsigned int old = atomicInc(&g_count, GRID - 1);
        is_last = (old == GRID - 1);
    }
    __syncthreads();

    if (!is_last) return;

    double sL = 0.0, s1d = 0.0, s2d = 0.0;
    for (int k = tid; k < GRID; k += TPB) {
        sL  += (double)__ldcg(&g_part_nll[k]);
        s1d += (double)__ldcg(&g_part_w1[k]);
        s2d += (double)__ldcg(&g_part_w2[k]);
    }
    __shared__ double dL[8], d1[8], d2[8];
    sL = warp_red_d(sL); s1d = warp_red_d(s1d); s2d = warp_red_d(s2d);
    if (lane == 0) { dL[wrp] = sL; d1[wrp] = s1d; d2[wrp] = s2d; }
    __syncthreads();
    if (tid == 0) {
        double vL = 0.0, v1 = 0.0, v2 = 0.0;
        #pragma unroll
        for (int k = 0; k < 8; k++) { vL += dL[k]; v1 += d1[k]; v2 += d2[k]; }
        double nll = -vL * 0.6931471805599453 * invN;   // log2 -> ln
        double reg = 0.002 * (sqrt(v1) + sqrt(v2));
        out[0] = (float)(nll + reg);
    }
}

extern "C" void kernel_launch(void* const* d_in, const int* in_sizes, int n_in,
                              void* d_out, int out_size) {
    const float4* p4 = (const float4*)d_in[0];   // output_1: N float32
    const uint4*  l4 = (const uint4*)d_in[1];    // label: N int32
    const float4* w1 = (const float4*)d_in[2];
    const float4* w2 = (const float4*)d_in[3];
    const int nq  = in_sizes[0] / 4;
    const int nw1 = in_sizes[2] / 4;
    const int nw2 = in_sizes[3] / 4;
    const int chunk_n  = (nq  + NB_N  - 1) / NB_N;
    const int chunk_w1 = (nw1 + NB_W1 - 1) / NB_W1;
    const int nb_w2    = GRID - NB_N - NB_W1;
    const int chunk_w2 = (nw2 + nb_w2 - 1) / nb_w2;
    const double invN = 1.0 / (double)in_sizes[0];

    fused_kernel<<<GRID, TPB>>>(p4, l4, w1, w2, (float*)d_out,
                                nq, nw1, nw2, chunk_n, chunk_w1, chunk_w2, invN);
}

// round 11
// speedup vs baseline: 1.0387x; 1.0387x over previous
#include <cuda_runtime.h>
#include <math.h>

#define GRID  592            /* 148 SMs x 4 CTAs: one exact wave at occ 4 */
#define TPB   256
#define NB_N  472            /* NLL blocks; W1 next 60; W2 last 60 */
#define NB_W1 60

#define FIX_SCALE 268435456.0   /* 2^28 fixed-point scale */

__device__ unsigned long long g_sum_nll = 0;  // signed fixed-point via 2's complement
__device__ unsigned long long g_sum_w1  = 0;
__device__ unsigned long long g_sum_w2  = 0;
__device__ unsigned int g_count = 0;          // atomicInc wraps to 0 each launch

// log2(picked): picked = label ? p : 1-p, clamped at 1e-8.
// x = p + g, g = l ? +0.0f : -1.0f via carry-wrapping IMAD; picked = |x|.
static __device__ __forceinline__ float pick_lg2(float p, unsigned int l) {
    float g = __uint_as_float(l * 0x40800000u + 0xBF800000u);
    float pick = fmaxf(fabsf(p + g), 1e-8f);
    return __log2f(pick);
}
static __device__ __forceinline__ float e4(float4 p, uint4 l) {
    return (pick_lg2(p.x, l.x) + pick_lg2(p.y, l.y))
         + (pick_lg2(p.z, l.z) + pick_lg2(p.w, l.w));
}
static __device__ __forceinline__ float sq4(float4 v, float a) {
    a = fmaf(v.x, v.x, a); a = fmaf(v.y, v.y, a);
    a = fmaf(v.z, v.z, a); a = fmaf(v.w, v.w, a);
    return a;
}
static __device__ __forceinline__ float warp_red(float v) {
    #pragma unroll
    for (int o = 16; o; o >>= 1) v += __shfl_down_sync(0xFFFFFFFFu, v, o);
    return v;
}

// Sum of squares over [base, end) float4 groups, thread-strided, unroll x4.
static __device__ __forceinline__ float sumsq_range(const float4* __restrict__ w,
                                                    int base, int end) {
    float b0 = 0.0f, b1 = 0.0f, b2 = 0.0f, b3 = 0.0f;
    int i = base + threadIdx.x;
    for (; i + 3 * TPB < end; i += 4 * TPB) {
        float4 va = __ldcs(w + i);
        float4 vb = __ldcs(w + i + TPB);
        float4 vc = __ldcs(w + i + 2 * TPB);
        float4 vd = __ldcs(w + i + 3 * TPB);
        b0 = sq4(va, b0); b1 = sq4(vb, b1);
        b2 = sq4(vc, b2); b3 = sq4(vd, b3);
    }
    for (; i < end; i += TPB) {
        b0 = sq4(__ldcs(w + i), b0);
    }
    return (b0 + b1) + (b2 + b3);
}

extern "C" __global__ void __launch_bounds__(TPB, 4)
fused_kernel(const float4* __restrict__ p4,
             const uint4*  __restrict__ l4,
             const float4* __restrict__ w1,
             const float4* __restrict__ w2,
             float* __restrict__ out,
             int nq, int nw1, int nw2,
             int chunk_n, int chunk_w1, int chunk_w2, double invN) {
    const int bid = blockIdx.x;
    const int tid = threadIdx.x;

    float accL = 0.0f, a1 = 0.0f, a2 = 0.0f;

    if (bid < NB_N) {
        // NLL stream: contiguous chunk, thread-strided, unroll x4 (8 LDG.128/round).
        const int base = bid * chunk_n;
        const int end  = min(nq, base + chunk_n);
        float acc0 = 0.0f, acc1 = 0.0f, acc2 = 0.0f, acc3 = 0.0f;
        int i = base + tid;
        for (; i + 3 * TPB < end; i += 4 * TPB) {
            float4 pa = __ldcs(p4 + i);
            float4 pb = __ldcs(p4 + i + TPB);
            float4 pc = __ldcs(p4 + i + 2 * TPB);
            float4 pd = __ldcs(p4 + i + 3 * TPB);
            uint4  la = __ldcs(l4 + i);
            uint4  lb = __ldcs(l4 + i + TPB);
            uint4  lc = __ldcs(l4 + i + 2 * TPB);
            uint4  ld = __ldcs(l4 + i + 3 * TPB);
            acc0 += e4(pa, la);
            acc1 += e4(pb, lb);
            acc2 += e4(pc, lc);
            acc3 += e4(pd, ld);
        }
        for (; i < end; i += TPB) {
            float4 pa = __ldcs(p4 + i);
            uint4  la = __ldcs(l4 + i);
            acc0 += e4(pa, la);
        }
        accL = (acc0 + acc1) + (acc2 + acc3);   // sum of log2(picked)
    } else if (bid < NB_N + NB_W1) {
        const int b = bid - NB_N;
        a1 = sumsq_range(w1, b * chunk_w1, min(nw1, b * chunk_w1 + chunk_w1));
    } else {
        const int b = bid - NB_N - NB_W1;
        a2 = sumsq_range(w2, b * chunk_w2, min(nw2, b * chunk_w2 + chunk_w2));
    }

    // Block reduction.
    __shared__ float shL[8], sh1[8], sh2[8];
    const int lane = tid & 31;
    const int wrp  = tid >> 5;
    accL = warp_red(accL);
    a1   = warp_red(a1);
    a2   = warp_red(a2);
    if (lane == 0) { shL[wrp] = accL; sh1[wrp] = a1; sh2[wrp] = a2; }
    __syncthreads();
    if (tid == 0) {
        float vL = 0.0f, v1 = 0.0f, v2 = 0.0f;
        #pragma unroll
        for (int k = 0; k < 8; k++) { vL += shL[k]; v1 += sh1[k]; v2 += sh2[k]; }

        // Deterministic accumulation: signed 2^28 fixed point via u64 2's-complement
        // atomics (integer add is associative -> order-independent result).
        long long fL = llrint((double)vL * FIX_SCALE);
        long long f1 = llrint((double)v1 * FIX_SCALE);
        long long f2 = llrint((double)v2 * FIX_SCALE);
        atomicAdd(&g_sum_nll, (unsigned long long)fL);
        atomicAdd(&g_sum_w1,  (unsigned long long)f1);
        atomicAdd(&g_sum_w2,  (unsigned long long)f2);
        __threadfence();
        unsigned int old = atomicInc(&g_count, GRID - 1);
        if (old == GRID - 1) {
            // Last arriver: finish and reset totals for the next graph replay.
            __threadfence();
            long long tL = (long long)atomicAdd(&g_sum_nll, 0ULL);
            long long t1 = (long long)atomicAdd(&g_sum_w1, 0ULL);
            long long t2 = (long long)atomicAdd(&g_sum_w2, 0ULL);
            double sL = (double)tL / FIX_SCALE;
            double s1 = (double)t1 / FIX_SCALE;
            double s2 = (double)t2 / FIX_SCALE;
            double nll = -sL * 0.6931471805599453 * invN;   // log2 -> ln
            double reg = 0.002 * (sqrt(s1) + sqrt(s2));
            out[0] = (float)(nll + reg);
            g_sum_nll = 0ULL;
            g_sum_w1  = 0ULL;
            g_sum_w2  = 0ULL;
        }
    }
}

extern "C" void kernel_launch(void* const* d_in, const int* in_sizes, int n_in,
                              void* d_out, int out_size) {
    const float4* p4 = (const float4*)d_in[0];   // output_1: N float32
    const uint4*  l4 = (const uint4*)d_in[1];    // label: N int32
    const float4* w1 = (const float4*)d_in[2];
    const float4* w2 = (const float4*)d_in[3];
    const int nq  = in_sizes[0] / 4;
    const int nw1 = in_sizes[2] / 4;
    const int nw2 = in_sizes[3] / 4;
    const int chunk_n  = (nq  + NB_N  - 1) / NB_N;
    const int chunk_w1 = (nw1 + NB_W1 - 1) / NB_W1;
    const int nb_w2    = GRID - NB_N - NB_W1;
    const int chunk_w2 = (nw2 + nb_w2 - 1) / nb_w2;
    const double invN = 1.0 / (double)in_sizes[0];

    fused_kernel<<<GRID, TPB>>>(p4, l4, w1, w2, (float*)d_out,
                                nq, nw1, nw2, chunk_n, chunk_w1, chunk_w2, invN);
}

// round 13
// speedup vs baseline: 1.1022x; 1.0611x over previous
#include <cuda_runtime.h>
#include <math.h>

#define GRID  592            /* 148 SMs x 4 CTAs: one exact wave at occ 4 */
#define TPB   256
#define NB_N  472            /* NLL blocks; W1 next 60; W2 last 60 */
#define NB_W1 60

#define FIX_SCALE 268435456.0   /* 2^28 fixed-point scale */

__device__ unsigned long long g_sum_nll = 0;  // signed fixed-point, 2's complement
__device__ unsigned long long g_sum_w1  = 0;
__device__ unsigned long long g_sum_w2  = 0;
__device__ unsigned int g_count = 0;          // atomicInc wraps to 0 each launch

// 256-bit loads (sm_100+): one LDG.E.256 instead of two LDG.E.128.
static __device__ __forceinline__ void ldg256_f(const float* p, float* r) {
    asm("ld.global.nc.v8.f32 {%0,%1,%2,%3,%4,%5,%6,%7}, [%8];"
        : "=f"(r[0]), "=f"(r[1]), "=f"(r[2]), "=f"(r[3]),
          "=f"(r[4]), "=f"(r[5]), "=f"(r[6]), "=f"(r[7])
        : "l"(p));
}
static __device__ __forceinline__ void ldg256_u(const unsigned* p, unsigned* r) {
    asm("ld.global.nc.v8.b32 {%0,%1,%2,%3,%4,%5,%6,%7}, [%8];"
        : "=r"(r[0]), "=r"(r[1]), "=r"(r[2]), "=r"(r[3]),
          "=r"(r[4]), "=r"(r[5]), "=r"(r[6]), "=r"(r[7])
        : "l"(p));
}

// log2(picked): picked = label ? p : 1-p, clamped at 1e-8.
// x = p + g, g = l ? +0.0f : -1.0f via carry-wrapping IMAD; picked = |x|.
static __device__ __forceinline__ float pick_lg2(float p, unsigned int l) {
    float g = __uint_as_float(l * 0x40800000u + 0xBF800000u);
    float pick = fmaxf(fabsf(p + g), 1e-8f);
    return __log2f(pick);
}
static __device__ __forceinline__ float warp_red(float v) {
    #pragma unroll
    for (int o = 16; o; o >>= 1) v += __shfl_down_sync(0xFFFFFFFFu, v, o);
    return v;
}

extern "C" __global__ void __launch_bounds__(TPB, 4)
fused_kernel(const float*    __restrict__ pf,
             const unsigned* __restrict__ lu,
             const float*    __restrict__ w1f,
             const float*    __restrict__ w2f,
             float* __restrict__ out,
             int nq8, int nw18, int nw28,
             int chunk_n, int chunk_w1, int chunk_w2, double invN) {
    const int bid = blockIdx.x;
    const int tid = threadIdx.x;

    float accL = 0.0f, a1 = 0.0f, a2 = 0.0f;

    if (bid < NB_N) {
        // NLL stream: contiguous chunk of v8 groups, thread-strided.
        const int base = bid * chunk_n;
        const int end  = min(nq8, base + chunk_n);
        float acc0 = 0.0f, acc1 = 0.0f;
        for (int i = base + tid; i < end; i += TPB) {
            float    p[8];
            unsigned l[8];
            ldg256_f(pf + (size_t)i * 8, p);
            ldg256_u(lu + (size_t)i * 8, l);
            acc0 += (pick_lg2(p[0], l[0]) + pick_lg2(p[1], l[1]))
                  + (pick_lg2(p[2], l[2]) + pick_lg2(p[3], l[3]));
            acc1 += (pick_lg2(p[4], l[4]) + pick_lg2(p[5], l[5]))
                  + (pick_lg2(p[6], l[6]) + pick_lg2(p[7], l[7]));
        }
        accL = acc0 + acc1;   // sum of log2(picked)
    } else {
        // W sum-of-squares stream, v8 loads, unroll x2.
        const bool isW1 = (bid < NB_N + NB_W1);
        const float* w  = isW1 ? w1f : w2f;
        const int bb    = isW1 ? (bid - NB_N) : (bid - NB_N - NB_W1);
        const int ch    = isW1 ? chunk_w1 : chunk_w2;
        const int nw    = isW1 ? nw18 : nw28;
        const int base  = bb * ch;
        const int end   = min(nw, base + ch);
        float s0 = 0.0f, s1 = 0.0f;
        int i = base + tid;
        for (; i + TPB < end; i += 2 * TPB) {
            float va[8], vb[8];
            ldg256_f(w + (size_t)i * 8, va);
            ldg256_f(w + (size_t)(i + TPB) * 8, vb);
            #pragma unroll
            for (int k = 0; k < 8; k++) s0 = fmaf(va[k], va[k], s0);
            #pragma unroll
            for (int k = 0; k < 8; k++) s1 = fmaf(vb[k], vb[k], s1);
        }
        if (i < end) {
            float va[8];
            ldg256_f(w + (size_t)i * 8, va);
            #pragma unroll
            for (int k = 0; k < 8; k++) s0 = fmaf(va[k], va[k], s0);
        }
        float sw = s0 + s1;
        if (isW1) a1 = sw; else a2 = sw;
    }

    // Block reduction.
    __shared__ float shL[8], sh1[8], sh2[8];
    const int lane = tid & 31;
    const int wrp  = tid >> 5;
    accL = warp_red(accL);
    a1   = warp_red(a1);
    a2   = warp_red(a2);
    if (lane == 0) { shL[wrp] = accL; sh1[wrp] = a1; sh2[wrp] = a2; }
    __syncthreads();
    if (tid == 0) {
        float vL = 0.0f, v1 = 0.0f, v2 = 0.0f;
        #pragma unroll
        for (int k = 0; k < 8; k++) { vL += shL[k]; v1 += sh1[k]; v2 += sh2[k]; }

        // Deterministic accumulation: signed 2^28 fixed point via u64 atomics
        // (integer add is associative -> order-independent result).
        long long fL = llrint((double)vL * FIX_SCALE);
        long long f1 = llrint((double)v1 * FIX_SCALE);
        long long f2 = llrint((double)v2 * FIX_SCALE);
        atomicAdd(&g_sum_nll, (unsigned long long)fL);
        atomicAdd(&g_sum_w1,  (unsigned long long)f1);
        atomicAdd(&g_sum_w2,  (unsigned long long)f2);
        __threadfence();
        unsigned int old = atomicInc(&g_count, GRID - 1);
        if (old == GRID - 1) {
            // Last arriver: finish and reset totals for the next graph replay.
            __threadfence();
            long long tL = (long long)atomicAdd(&g_sum_nll, 0ULL);
            long long t1 = (long long)atomicAdd(&g_sum_w1, 0ULL);
            long long t2 = (long long)atomicAdd(&g_sum_w2, 0ULL);
            double sL = (double)tL / FIX_SCALE;
            double s1 = (double)t1 / FIX_SCALE;
            double s2 = (double)t2 / FIX_SCALE;
            double nll = -sL * 0.6931471805599453 * invN;   // log2 -> ln
            double reg = 0.002 * (sqrt(s1) + sqrt(s2));
            out[0] = (float)(nll + reg);
            g_sum_nll = 0ULL;
            g_sum_w1  = 0ULL;
            g_sum_w2  = 0ULL;
        }
    }
}

extern "C" void kernel_launch(void* const* d_in, const int* in_sizes, int n_in,
                              void* d_out, int out_size) {
    const float*    pf = (const float*)d_in[0];     // output_1: N float32
    const unsigned* lu = (const unsigned*)d_in[1];  // label: N int32
    const float*    w1 = (const float*)d_in[2];
    const float*    w2 = (const float*)d_in[3];
    const int nq8  = in_sizes[0] / 8;   // v8 groups
    const int nw18 = in_sizes[2] / 8;
    const int nw28 = in_sizes[3] / 8;
    const int chunk_n  = (nq8  + NB_N  - 1) / NB_N;
    const int chunk_w1 = (nw18 + NB_W1 - 1) / NB_W1;
    const int nb_w2    = GRID - NB_N - NB_W1;
    const int chunk_w2 = (nw28 + nb_w2 - 1) / nb_w2;
    const double invN = 1.0 / (double)in_sizes[0];

    fused_kernel<<<GRID, TPB>>>(pf, lu, w1, w2, (float*)d_out,
                                nq8, nw18, nw28,
                                chunk_n, chunk_w1, chunk_w2, invN);
}